// round 1
// baseline (speedup 1.0000x reference)
#include <cuda_runtime.h>

#define NN 50000
#define NE 600000
#define H  128
#define HV4 32          // H/4
#define GG 16
#define OUTD 14
#define NL 3
#define GEN_EPS 1e-7f
#define BN_EPS  1e-5f
#define BN_BLOCKS 256
#define BN_CHUNK  196   // ceil(50000/256)

// ---------------- scratch (device globals; no allocation allowed) ------------
__device__ float g_hv [NN * H];
__device__ float g_hv1[NN * H];
__device__ float g_x  [NN * H];
__device__ int   g_cnt[NN];
__device__ int   g_off[NN + 1];
__device__ int   g_edge[NE];                  // packed: src | f0<<16 | f1<<19
__device__ float g_part[2][BN_BLOCKS][H];
__device__ float g_scale[H];
__device__ float g_shift[H];
__device__ float g_hg[GG * H];
__device__ int   g_cntg[GG];

// ---------------- init -------------------------------------------------------
__global__ void k_zero() {
    int i = blockIdx.x * blockDim.x + threadIdx.x;
    if (i < NN)     g_cnt[i] = 0;
    if (i < GG * H) g_hg[i] = 0.f;
    if (i < GG)     g_cntg[i] = 0;
}

// node embedding: hv = Wn0[f0] + Wn1[f1]
__global__ void k_embed(const int* __restrict__ f0, const int* __restrict__ f1,
                        const float* __restrict__ W0, const float* __restrict__ W1) {
    int i = blockIdx.x * blockDim.x + threadIdx.x;   // over NN*HV4 float4s
    if (i >= NN * HV4) return;
    int n = i >> 5, q = i & 31;
    float4 a = ((const float4*)W0)[f0[n] * HV4 + q];
    float4 b = ((const float4*)W1)[f1[n] * HV4 + q];
    float4 r = make_float4(a.x + b.x, a.y + b.y, a.z + b.z, a.w + b.w);
    ((float4*)g_hv)[i] = r;
}

// ---------------- CSR build (dst-sorted), once per launch --------------------
__global__ void k_count(const int* __restrict__ dst) {
    int e = blockIdx.x * blockDim.x + threadIdx.x;
    if (e < NE) atomicAdd(&g_cnt[dst[e]], 1);
}

__global__ void k_scan() {   // one block, 1024 threads, chunked exclusive scan
    __shared__ int sm[1024];
    const int CH = (NN + 1023) / 1024;   // 49
    int t = threadIdx.x;
    int base = t * CH;
    int s = 0;
    for (int i = 0; i < CH; i++) { int idx = base + i; if (idx < NN) s += g_cnt[idx]; }
    sm[t] = s;
    __syncthreads();
    for (int d = 1; d < 1024; d <<= 1) {
        int v = (t >= d) ? sm[t - d] : 0;
        __syncthreads();
        sm[t] += v;
        __syncthreads();
    }
    int run = sm[t] - s;   // exclusive prefix of this chunk
    for (int i = 0; i < CH; i++) {
        int idx = base + i;
        if (idx < NN) { g_off[idx] = run; run += g_cnt[idx]; }
    }
    if (t == 1023) g_off[NN] = sm[1023];
}

// scatter edges; uses g_off itself as cursor (post: g_off[v] = segment END,
// start = g_off[v] - g_cnt[v])
__global__ void k_scatter(const int* __restrict__ src, const int* __restrict__ dst,
                          const int* __restrict__ f0, const int* __restrict__ f1) {
    int e = blockIdx.x * blockDim.x + threadIdx.x;
    if (e >= NE) return;
    int d = dst[e];
    int j = atomicAdd(&g_off[d], 1);
    g_edge[j] = src[e] | (f0[e] << 16) | (f1[e] << 19);
}

// ---------------- BatchNorm --------------------------------------------------
__global__ void k_bnpart() {
    int b = blockIdx.x, c = threadIdx.x;
    int n0 = b * BN_CHUNK;
    int n1 = min(NN, n0 + BN_CHUNK);
    float s = 0.f, ss = 0.f;
    for (int n = n0; n < n1; n++) { float v = g_hv[n * H + c]; s += v; ss += v * v; }
    g_part[0][b][c] = s;
    g_part[1][b][c] = ss;
}

__global__ void k_bnfin(const float* __restrict__ gamma, const float* __restrict__ bnb, int l) {
    int c = threadIdx.x;
    float s = 0.f, ss = 0.f;
    for (int b = 0; b < BN_BLOCKS; b++) { s += g_part[0][b][c]; ss += g_part[1][b][c]; }
    float mu  = s / (float)NN;
    float var = ss / (float)NN - mu * mu;
    float sc  = rsqrtf(var + BN_EPS) * gamma[l * H + c];
    g_scale[c] = sc;
    g_shift[c] = bnb[l * H + c] - mu * sc;
}

__global__ void k_bnapply() {
    int i = blockIdx.x * blockDim.x + threadIdx.x;
    if (i >= NN * HV4) return;
    int q = i & 31;
    float4 v  = ((const float4*)g_hv)[i];
    float4 sc = ((const float4*)g_scale)[q];
    float4 sh = ((const float4*)g_shift)[q];
    float4 r;
    r.x = fmaxf(v.x * sc.x + sh.x, 0.f);
    r.y = fmaxf(v.y * sc.y + sh.y, 0.f);
    r.z = fmaxf(v.z * sc.z + sh.z, 0.f);
    r.w = fmaxf(v.w * sc.w + sh.w, 0.f);
    ((float4*)g_hv1)[i] = r;
}

// ---------------- GENConv aggregation: warp per dst node ---------------------
// agg = sum(m*e)/sum(e) with e = exp(m*beta); max-shift omitted (z in (0,~10],
// no overflow; ratio is shift-invariant). x = hv1 + agg written directly.
__global__ void k_agg(const float* __restrict__ ee0, const float* __restrict__ ee1,
                      const float* __restrict__ beta, int l) {
    int gt   = blockIdx.x * blockDim.x + threadIdx.x;
    int wid  = gt >> 5;
    int lane = threadIdx.x & 31;
    if (wid >= NN) return;
    float bl = beta[l];
    int end = g_off[wid];
    int beg = end - g_cnt[wid];
    const float4* hv1_4 = (const float4*)g_hv1;
    const float4* e0_4  = (const float4*)(ee0 + (size_t)l * 6 * H);
    const float4* e1_4  = (const float4*)(ee1 + (size_t)l * 3 * H);
    float4 num = make_float4(0.f, 0.f, 0.f, 0.f);
    float4 den = make_float4(0.f, 0.f, 0.f, 0.f);
    for (int j = beg; j < end; j++) {
        int pe  = g_edge[j];
        int src = pe & 0xFFFF;
        int f0  = (pe >> 16) & 7;
        int f1  = (pe >> 19) & 3;
        float4 h = hv1_4[src * HV4 + lane];
        float4 a = e0_4[f0 * HV4 + lane];
        float4 b = e1_4[f1 * HV4 + lane];
        float m, ex;
        m = fmaxf(h.x + a.x + b.x, 0.f) + GEN_EPS; ex = expf(m * bl); den.x += ex; num.x += m * ex;
        m = fmaxf(h.y + a.y + b.y, 0.f) + GEN_EPS; ex = expf(m * bl); den.y += ex; num.y += m * ex;
        m = fmaxf(h.z + a.z + b.z, 0.f) + GEN_EPS; ex = expf(m * bl); den.z += ex; num.z += m * ex;
        m = fmaxf(h.w + a.w + b.w, 0.f) + GEN_EPS; ex = expf(m * bl); den.w += ex; num.w += m * ex;
    }
    float4 xo = hv1_4[wid * HV4 + lane];
    if (end > beg) {
        xo.x += num.x / den.x;
        xo.y += num.y / den.y;
        xo.z += num.z / den.z;
        xo.w += num.w / den.w;
    }
    ((float4*)g_x)[wid * HV4 + lane] = xo;
}

// ---------------- MLP GEMM: hv = x @ W + b + hv (in place) -------------------
// 64-row tile, 256 threads, 4x8 register blocking, k-chunked smem staging.
__global__ void __launch_bounds__(256) k_gemm(const float* __restrict__ W,
                                              const float* __restrict__ bias) {
    __shared__ float Ws[32 * H];       // 16 KB
    __shared__ float Xs[64 * 36];      // 9 KB (pad 36 vs conflicts)
    int tid = threadIdx.x;
    int tx = tid & 15, ty = tid >> 4;
    int row0 = blockIdx.x * 64;
    float acc[4][8];
#pragma unroll
    for (int i = 0; i < 4; i++)
#pragma unroll
        for (int j = 0; j < 8; j++) acc[i][j] = 0.f;

    for (int kk = 0; kk < H; kk += 32) {
        const float4* Wg  = (const float4*)(W + kk * H);
        float4*       Ws4 = (float4*)Ws;
#pragma unroll
        for (int i = 0; i < 4; i++) Ws4[tid + i * 256] = Wg[tid + i * 256];
#pragma unroll
        for (int i = 0; i < 2; i++) {
            int f  = tid + i * 256;     // 0..511 float4s
            int r  = f >> 3, c4 = f & 7;
            int row = row0 + r;
            float4 v = make_float4(0.f, 0.f, 0.f, 0.f);
            if (row < NN) v = ((const float4*)(g_x + row * H + kk))[c4];
            ((float4*)(Xs + r * 36))[c4] = v;
        }
        __syncthreads();
#pragma unroll
        for (int k = 0; k < 32; k++) {
            float a[4];
#pragma unroll
            for (int i = 0; i < 4; i++) a[i] = Xs[(ty * 4 + i) * 36 + k];
            float4 b0 = *(const float4*)&Ws[k * H + tx * 8];
            float4 b1 = *(const float4*)&Ws[k * H + tx * 8 + 4];
            float b[8] = {b0.x, b0.y, b0.z, b0.w, b1.x, b1.y, b1.z, b1.w};
#pragma unroll
            for (int i = 0; i < 4; i++)
#pragma unroll
                for (int j = 0; j < 8; j++) acc[i][j] += a[i] * b[j];
        }
        __syncthreads();
    }
#pragma unroll
    for (int i = 0; i < 4; i++) {
        int row = row0 + ty * 4 + i;
        if (row < NN) {
            float* hr = g_hv + row * H + tx * 8;
            const float* br = bias + tx * 8;
#pragma unroll
            for (int j = 0; j < 8; j++) hr[j] = acc[i][j] + br[j] + hr[j];
        }
    }
}

// ---------------- graph pooling + output head --------------------------------
__global__ void k_pool(const int* __restrict__ gid) {
    int b = blockIdx.x, c = threadIdx.x;
    int n0 = b * BN_CHUNK;
    int n1 = min(NN, n0 + BN_CHUNK);
    if (n0 >= NN) return;
    float acc = 0.f;
    int curg = gid[n0];
    int run = 0;
    for (int n = n0; n < n1; n++) {
        int g = gid[n];
        if (g != curg) {
            atomicAdd(&g_hg[curg * H + c], acc);
            if (c == 0) atomicAdd(&g_cntg[curg], run);
            acc = 0.f; run = 0; curg = g;
        }
        acc += g_hv[n * H + c];
        run++;
    }
    atomicAdd(&g_hg[curg * H + c], acc);
    if (c == 0) atomicAdd(&g_cntg[curg], run);
}

__global__ void k_out(const float* __restrict__ Wo, const float* __restrict__ bo,
                      float* __restrict__ out) {
    int t = threadIdx.x;
    if (t >= GG * OUTD) return;
    int g = t / OUTD, o = t % OUTD;
    float inv = 1.f / (float)g_cntg[g];
    float acc = bo[o];
    for (int h = 0; h < H; h++) acc += g_hg[g * H + h] * inv * Wo[h * OUTD + o];
    out[t] = acc;
}

// ---------------- launch -----------------------------------------------------
extern "C" void kernel_launch(void* const* d_in, const int* in_sizes, int n_in,
                              void* d_out, int out_size) {
    const int* nf0  = (const int*)d_in[0];
    const int* nf1  = (const int*)d_in[1];
    const int* ef0  = (const int*)d_in[2];
    const int* ef1  = (const int*)d_in[3];
    const int* esrc = (const int*)d_in[4];
    const int* edst = (const int*)d_in[5];
    const int* gid  = (const int*)d_in[6];
    // num_graphs may appear as a size-1 scalar input at index 7
    int base = (n_in > 7 && in_sizes[7] == 1) ? 8 : 7;
    const float* Wn0  = (const float*)d_in[base + 0];
    const float* Wn1  = (const float*)d_in[base + 1];
    const float* ee0  = (const float*)d_in[base + 2];
    const float* ee1  = (const float*)d_in[base + 3];
    const float* beta = (const float*)d_in[base + 4];
    const float* mlpW = (const float*)d_in[base + 5];
    const float* mlpb = (const float*)d_in[base + 6];
    const float* gam  = (const float*)d_in[base + 7];
    const float* bnb  = (const float*)d_in[base + 8];
    const float* Wo   = (const float*)d_in[base + 9];
    const float* bo   = (const float*)d_in[base + 10];
    float* out = (float*)d_out;

    k_zero<<<196, 256>>>();
    k_embed<<<(NN * HV4 + 255) / 256, 256>>>(nf0, nf1, Wn0, Wn1);
    k_count<<<(NE + 255) / 256, 256>>>(edst);
    k_scan<<<1, 1024>>>();
    k_scatter<<<(NE + 255) / 256, 256>>>(esrc, edst, ef0, ef1);

    for (int l = 0; l < NL; l++) {
        k_bnpart<<<BN_BLOCKS, H>>>();
        k_bnfin<<<1, H>>>(gam, bnb, l);
        k_bnapply<<<(NN * HV4 + 255) / 256, 256>>>();
        k_agg<<<(NN * 32 + 255) / 256, 256>>>(ee0, ee1, beta, l);
        k_gemm<<<(NN + 63) / 64, 256>>>(mlpW + (size_t)l * H * H, mlpb + (size_t)l * H);
    }

    k_pool<<<BN_BLOCKS, H>>>(gid);
    k_out<<<1, 256>>>(Wo, bo, out);
}

// round 2
// speedup vs baseline: 1.2791x; 1.2791x over previous
#include <cuda_runtime.h>

#define NN 50000
#define NE 600000
#define H  128
#define HV4 32          // H/4
#define GG 16
#define OUTD 14
#define NL 3
#define GEN_EPS 1e-7f
#define BN_EPS  1e-5f
#define BN_BLOCKS 256
#define BN_CHUNK  196     // ceil(50000/256)
#define NBC 391           // ceil(NN/128)  (embed / scan blocks)
#define NBG 782           // ceil(NN/64)   (gemm blocks)
#define MAXPART 800

// ---------------- scratch (device globals; no allocation allowed) ------------
__device__ float g_hv [NN * H];
__device__ float g_x  [NN * H];
__device__ int   g_cnt[NN];
__device__ int   g_off[NN];
__device__ int   g_bsum[512];
__device__ int   g_boff[512];
__device__ int   g_edge[NE];                  // packed: src | (f0*3+f1)<<16
__device__ float g_part[2][MAXPART][H];
__device__ float g_scale[H];
__device__ float g_shift[H];
__device__ float g_etab[18 * H];
__device__ float g_hg[GG * H];
__device__ int   g_cntg[GG];

// ---------------- init -------------------------------------------------------
__global__ void k_zero() {
    int i = blockIdx.x * blockDim.x + threadIdx.x;
    if (i < NN)     g_cnt[i] = 0;
    if (i < GG * H) g_hg[i] = 0.f;
    if (i < GG)     g_cntg[i] = 0;
}

// node embedding + BN partial stats.  block = 128 nodes, thread = 1 channel.
__global__ void k_embed(const int* __restrict__ f0, const int* __restrict__ f1,
                        const float* __restrict__ W0, const float* __restrict__ W1) {
    __shared__ int sf0[128], sf1[128];
    int b = blockIdx.x, c = threadIdx.x;
    int n0 = b * 128;
    int cnt = min(128, NN - n0);
    if (c < cnt) { sf0[c] = f0[n0 + c]; sf1[c] = f1[n0 + c]; }
    __syncthreads();
    float s = 0.f, ss = 0.f;
    for (int i = 0; i < cnt; i++) {
        float v = W0[sf0[i] * H + c] + W1[sf1[i] * H + c];
        g_hv[(n0 + i) * H + c] = v;
        s += v; ss += v * v;
    }
    g_part[0][b][c] = s;
    g_part[1][b][c] = ss;
}

// ---------------- CSR build (dst-sorted), hierarchical scan ------------------
__global__ void k_count(const int* __restrict__ dst) {
    int e = blockIdx.x * blockDim.x + threadIdx.x;
    if (e < NE) atomicAdd(&g_cnt[dst[e]], 1);
}

// per-block sums of g_cnt (128 per block)
__global__ void k_scan1() {
    __shared__ int wsum[4];
    int b = blockIdx.x, t = threadIdx.x;
    int idx = b * 128 + t;
    int v = (idx < NN) ? g_cnt[idx] : 0;
    int s = v;
    for (int d = 16; d > 0; d >>= 1) s += __shfl_down_sync(0xffffffffu, s, d);
    if ((t & 31) == 0) wsum[t >> 5] = s;
    __syncthreads();
    if (t == 0) g_bsum[b] = wsum[0] + wsum[1] + wsum[2] + wsum[3];
}

// exclusive scan of NBC block sums (single small block)
__global__ void k_scan2() {
    __shared__ int sm[512];
    int t = threadIdx.x;
    int v = (t < NBC) ? g_bsum[t] : 0;
    sm[t] = v;
    __syncthreads();
    for (int d = 1; d < 512; d <<= 1) {
        int u = (t >= d) ? sm[t - d] : 0;
        __syncthreads();
        sm[t] += u;
        __syncthreads();
    }
    if (t < NBC) g_boff[t] = sm[t] - v;
}

// per-block exclusive scan + add block offset -> g_off (segment starts)
__global__ void k_scan3() {
    __shared__ int wsum[4];
    int b = blockIdx.x, t = threadIdx.x;
    int idx = b * 128 + t;
    int v = (idx < NN) ? g_cnt[idx] : 0;
    int inc = v;
    for (int d = 1; d < 32; d <<= 1) {
        int u = __shfl_up_sync(0xffffffffu, inc, d);
        if ((t & 31) >= d) inc += u;
    }
    if ((t & 31) == 31) wsum[t >> 5] = inc;
    __syncthreads();
    int w = t >> 5;
    int woff = 0;
    for (int i = 0; i < 4; i++) if (i < w) woff += wsum[i];
    if (idx < NN) g_off[idx] = g_boff[b] + woff + inc - v;
}

// scatter edges; g_off used as cursor (post: g_off[v] = segment END)
__global__ void k_scatter(const int* __restrict__ src, const int* __restrict__ dst,
                          const int* __restrict__ f0, const int* __restrict__ f1) {
    int e = blockIdx.x * blockDim.x + threadIdx.x;
    if (e >= NE) return;
    int d = dst[e];
    int j = atomicAdd(&g_off[d], 1);
    g_edge[j] = src[e] | ((f0[e] * 3 + f1[e]) << 16);
}

// ---------------- BN finalize + combined edge table --------------------------
__global__ void k_bnfin(const float* __restrict__ gamma, const float* __restrict__ bnb,
                        const float* __restrict__ ee0, const float* __restrict__ ee1,
                        int l, int nblk) {
    __shared__ float red[2][8][H];
    int tid = threadIdx.x;
    int c = tid & 127, g = tid >> 7;
    float s = 0.f, ss = 0.f;
    for (int b = g; b < nblk; b += 8) { s += g_part[0][b][c]; ss += g_part[1][b][c]; }
    red[0][g][c] = s; red[1][g][c] = ss;
    __syncthreads();
    if (tid < H) {
        float S = 0.f, SS = 0.f;
        for (int i = 0; i < 8; i++) { S += red[0][i][tid]; SS += red[1][i][tid]; }
        float mu  = S / (float)NN;
        float var = SS / (float)NN - mu * mu;
        float sc  = rsqrtf(var + BN_EPS) * gamma[l * H + tid];
        g_scale[tid] = sc;
        g_shift[tid] = bnb[l * H + tid] - mu * sc;
    }
    for (int i = tid; i < 18 * H; i += 1024) {
        int idx = i >> 7, cc = i & 127;
        int f0 = idx / 3, f1 = idx - f0 * 3;
        g_etab[i] = ee0[(l * 6 + f0) * H + cc] + ee1[(l * 3 + f1) * H + cc];
    }
}

// ---------------- GENConv aggregation: warp per dst node ---------------------
// BN-apply fused on the fly (hv1 = relu(hv*sc+sh)).  agg = sum(m*e)/sum(e),
// e = exp(m*beta) (no max-shift needed: m in (0,~10]).  x = hv1 + agg.
__global__ void __launch_bounds__(256) k_agg(const float* __restrict__ beta, int l) {
    __shared__ float etab[18 * H];
    int tid = threadIdx.x;
    for (int i = tid; i < 18 * H; i += 256) etab[i] = g_etab[i];
    __syncthreads();
    int gt   = blockIdx.x * 256 + tid;
    int wid  = gt >> 5;
    int lane = tid & 31;
    if (wid >= NN) return;
    float bl = beta[l];
    int end = g_off[wid];
    int beg = end - g_cnt[wid];
    const float4* hv4 = (const float4*)g_hv;
    const float4* et4 = (const float4*)etab;
    float4 sc = ((const float4*)g_scale)[lane];
    float4 sh = ((const float4*)g_shift)[lane];
    float4 num = make_float4(0.f, 0.f, 0.f, 0.f);
    float4 den = make_float4(0.f, 0.f, 0.f, 0.f);
#define EDGE_ELEM(hc, ec, scc, shc, nc, dc) do {                         \
        float t_ = fmaxf(fmaf(hc, scc, shc), 0.f);                        \
        float m_ = fmaxf(t_ + ec, 0.f) + GEN_EPS;                         \
        float x_ = __expf(m_ * bl);                                       \
        dc += x_; nc = fmaf(m_, x_, nc); } while (0)
#define EDGE_ONE(pe) do {                                                 \
        int src_ = (pe) & 0xFFFF;                                         \
        int idx_ = (pe) >> 16;                                            \
        float4 h_ = hv4[src_ * HV4 + lane];                               \
        float4 e_ = et4[idx_ * HV4 + lane];                               \
        EDGE_ELEM(h_.x, e_.x, sc.x, sh.x, num.x, den.x);                  \
        EDGE_ELEM(h_.y, e_.y, sc.y, sh.y, num.y, den.y);                  \
        EDGE_ELEM(h_.z, e_.z, sc.z, sh.z, num.z, den.z);                  \
        EDGE_ELEM(h_.w, e_.w, sc.w, sh.w, num.w, den.w); } while (0)
    int j = beg;
    for (; j + 2 <= end; j += 2) {
        int pe0 = g_edge[j], pe1 = g_edge[j + 1];
        EDGE_ONE(pe0);
        EDGE_ONE(pe1);
    }
    if (j < end) { int pe0 = g_edge[j]; EDGE_ONE(pe0); }
    float4 hr = hv4[wid * HV4 + lane];
    float4 xo;
    xo.x = fmaxf(fmaf(hr.x, sc.x, sh.x), 0.f);
    xo.y = fmaxf(fmaf(hr.y, sc.y, sh.y), 0.f);
    xo.z = fmaxf(fmaf(hr.z, sc.z, sh.z), 0.f);
    xo.w = fmaxf(fmaf(hr.w, sc.w, sh.w), 0.f);
    if (end > beg) {
        xo.x += num.x / den.x;
        xo.y += num.y / den.y;
        xo.z += num.z / den.z;
        xo.w += num.w / den.w;
    }
    ((float4*)g_x)[wid * HV4 + lane] = xo;
}

// ---------------- MLP GEMM: hv = x @ W + b + hv, + BN partial stats ----------
__global__ void __launch_bounds__(256) k_gemm(const float* __restrict__ W,
                                              const float* __restrict__ bias) {
    __shared__ float Ws[32 * H];       // 16 KB, reused for stat reduction
    __shared__ float Xs[64 * 36];      // 9 KB (padded)
    int tid = threadIdx.x;
    int tx = tid & 15, ty = tid >> 4;
    int row0 = blockIdx.x * 64;
    float acc[4][8];
#pragma unroll
    for (int i = 0; i < 4; i++)
#pragma unroll
        for (int j = 0; j < 8; j++) acc[i][j] = 0.f;

    for (int kk = 0; kk < H; kk += 32) {
        const float4* Wg  = (const float4*)(W + kk * H);
        float4*       Ws4 = (float4*)Ws;
#pragma unroll
        for (int i = 0; i < 4; i++) Ws4[tid + i * 256] = Wg[tid + i * 256];
#pragma unroll
        for (int i = 0; i < 2; i++) {
            int f  = tid + i * 256;
            int r  = f >> 3, c4 = f & 7;
            int row = row0 + r;
            float4 v = make_float4(0.f, 0.f, 0.f, 0.f);
            if (row < NN) v = ((const float4*)(g_x + row * H + kk))[c4];
            ((float4*)(Xs + r * 36))[c4] = v;
        }
        __syncthreads();
#pragma unroll
        for (int k = 0; k < 32; k++) {
            float a[4];
#pragma unroll
            for (int i = 0; i < 4; i++) a[i] = Xs[(ty * 4 + i) * 36 + k];
            float4 b0 = *(const float4*)&Ws[k * H + tx * 8];
            float4 b1 = *(const float4*)&Ws[k * H + tx * 8 + 4];
            float b[8] = {b0.x, b0.y, b0.z, b0.w, b1.x, b1.y, b1.z, b1.w};
#pragma unroll
            for (int i = 0; i < 4; i++)
#pragma unroll
                for (int j = 0; j < 8; j++) acc[i][j] += a[i] * b[j];
        }
        __syncthreads();
    }
    // epilogue: out = acc + bias + hv_old; accumulate BN partial stats
    float4 br0 = ((const float4*)(bias + tx * 8))[0];
    float4 br1 = ((const float4*)(bias + tx * 8))[1];
    float s_loc[8], ss_loc[8];
#pragma unroll
    for (int j = 0; j < 8; j++) { s_loc[j] = 0.f; ss_loc[j] = 0.f; }
#pragma unroll
    for (int i = 0; i < 4; i++) {
        int row = row0 + ty * 4 + i;
        if (row < NN) {
            float4* hr = (float4*)(g_hv + row * H + tx * 8);
            float4 h0 = hr[0], h1 = hr[1];
            float v[8];
            v[0] = acc[i][0] + br0.x + h0.x; v[1] = acc[i][1] + br0.y + h0.y;
            v[2] = acc[i][2] + br0.z + h0.z; v[3] = acc[i][3] + br0.w + h0.w;
            v[4] = acc[i][4] + br1.x + h1.x; v[5] = acc[i][5] + br1.y + h1.y;
            v[6] = acc[i][6] + br1.z + h1.z; v[7] = acc[i][7] + br1.w + h1.w;
            hr[0] = make_float4(v[0], v[1], v[2], v[3]);
            hr[1] = make_float4(v[4], v[5], v[6], v[7]);
#pragma unroll
            for (int j = 0; j < 8; j++) { s_loc[j] += v[j]; ss_loc[j] += v[j] * v[j]; }
        }
    }
    __syncthreads();
#pragma unroll
    for (int j = 0; j < 8; j++) {
        int ch = tx * 8 + j;
        Ws[ty * H + ch]        = s_loc[j];
        Ws[2048 + ty * H + ch] = ss_loc[j];
    }
    __syncthreads();
    if (tid < H) {
        float s = 0.f, ss = 0.f;
#pragma unroll
        for (int g = 0; g < 16; g++) { s += Ws[g * H + tid]; ss += Ws[2048 + g * H + tid]; }
        g_part[0][blockIdx.x][tid] = s;
        g_part[1][blockIdx.x][tid] = ss;
    }
}

// ---------------- graph pooling + output head --------------------------------
__global__ void k_pool(const int* __restrict__ gid) {
    int b = blockIdx.x, c = threadIdx.x;
    int n0 = b * BN_CHUNK;
    int n1 = min(NN, n0 + BN_CHUNK);
    if (n0 >= NN) return;
    float acc = 0.f;
    int curg = gid[n0];
    int run = 0;
    for (int n = n0; n < n1; n++) {
        int g = gid[n];
        if (g != curg) {
            atomicAdd(&g_hg[curg * H + c], acc);
            if (c == 0) atomicAdd(&g_cntg[curg], run);
            acc = 0.f; run = 0; curg = g;
        }
        acc += g_hv[n * H + c];
        run++;
    }
    atomicAdd(&g_hg[curg * H + c], acc);
    if (c == 0) atomicAdd(&g_cntg[curg], run);
}

__global__ void k_out(const float* __restrict__ Wo, const float* __restrict__ bo,
                      float* __restrict__ out) {
    int t = threadIdx.x;
    if (t >= GG * OUTD) return;
    int g = t / OUTD, o = t % OUTD;
    float inv = 1.f / (float)g_cntg[g];
    float acc = bo[o];
    for (int h = 0; h < H; h++) acc += g_hg[g * H + h] * inv * Wo[h * OUTD + o];
    out[t] = acc;
}

// ---------------- launch -----------------------------------------------------
extern "C" void kernel_launch(void* const* d_in, const int* in_sizes, int n_in,
                              void* d_out, int out_size) {
    const int* nf0  = (const int*)d_in[0];
    const int* nf1  = (const int*)d_in[1];
    const int* ef0  = (const int*)d_in[2];
    const int* ef1  = (const int*)d_in[3];
    const int* esrc = (const int*)d_in[4];
    const int* edst = (const int*)d_in[5];
    const int* gid  = (const int*)d_in[6];
    int base = (n_in > 7 && in_sizes[7] == 1) ? 8 : 7;
    const float* Wn0  = (const float*)d_in[base + 0];
    const float* Wn1  = (const float*)d_in[base + 1];
    const float* ee0  = (const float*)d_in[base + 2];
    const float* ee1  = (const float*)d_in[base + 3];
    const float* beta = (const float*)d_in[base + 4];
    const float* mlpW = (const float*)d_in[base + 5];
    const float* mlpb = (const float*)d_in[base + 6];
    const float* gam  = (const float*)d_in[base + 7];
    const float* bnb  = (const float*)d_in[base + 8];
    const float* Wo   = (const float*)d_in[base + 9];
    const float* bo   = (const float*)d_in[base + 10];
    float* out = (float*)d_out;

    k_zero<<<196, 256>>>();
    k_embed<<<NBC, 128>>>(nf0, nf1, Wn0, Wn1);
    k_count<<<(NE + 255) / 256, 256>>>(edst);
    k_scan1<<<NBC, 128>>>();
    k_scan2<<<1, 512>>>();
    k_scan3<<<NBC, 128>>>();
    k_scatter<<<(NE + 255) / 256, 256>>>(esrc, edst, ef0, ef1);

    for (int l = 0; l < NL; l++) {
        k_bnfin<<<1, 1024>>>(gam, bnb, ee0, ee1, l, l == 0 ? NBC : NBG);
        k_agg<<<(NN * 32 + 255) / 256, 256>>>(beta, l);
        k_gemm<<<NBG, 256>>>(mlpW + (size_t)l * H * H, mlpb + (size_t)l * H);
    }

    k_pool<<<BN_BLOCKS, H>>>(gid);
    k_out<<<1, 256>>>(Wo, bo, out);
}